// round 6
// baseline (speedup 1.0000x reference)
#include <cuda_runtime.h>
#include <cuda_bf16.h>

#define M_SZ    100
#define H_SZ    256
#define W_SZ    512
#define N_INST  64
#define C_THING 80
#define C_STUFF 53
#define C_OUT   (C_STUFF + N_INST)   // 117
#define WARPS_PB 8
#define ROWS_PW  4                    // rows per warp (divides H)

// One warp handles ROWS_PW consecutive rows of one channel. Per row: 128
// float4 -> lane l covers float4 columns l, l+32, l+64, l+96.
// Copy path batches loads across row pairs (MLP ~ 8). Box math once per warp.
__global__ __launch_bounds__(WARPS_PB * 32)
void panoptic_all_kernel(const float* __restrict__ mask_logits,   // [N, C_THING, M, M]
                         const float* __restrict__ sem_seg,       // [1, C_STUFF+C_THING, H, W]
                         const float* __restrict__ bbox,          // [N, 4]
                         const int*   __restrict__ cls_idx,       // [N]
                         float* __restrict__ out)                 // [1, C_OUT, H, W]
{
    const int warp = threadIdx.x >> 5;
    const int lane = threadIdx.x & 31;
    const int base_row = (blockIdx.x * WARPS_PB + warp) * ROWS_PW; // [0, C_OUT*H)
    const int c  = base_row >> 8;              // H == 256, groups don't cross channels
    const int y0 = base_row & (H_SZ - 1);

    float4* __restrict__ orow0 = (float4*)(out + (size_t)base_row * W_SZ);

    if (c < C_STUFF) {
        // stuff channels: copy 4 rows, two rows per batch (8 ld then 8 st)
        const float4* __restrict__ srow0 =
            (const float4*)(sem_seg + (size_t)base_row * W_SZ);
        #pragma unroll
        for (int p = 0; p < 2; ++p) {
            const float4* sa = srow0 + (2 * p)     * 128;
            const float4* sb = srow0 + (2 * p + 1) * 128;
            float4*       da = orow0 + (2 * p)     * 128;
            float4*       db = orow0 + (2 * p + 1) * 128;
            float4 a0 = sa[lane];      float4 a1 = sa[lane + 32];
            float4 a2 = sa[lane + 64]; float4 a3 = sa[lane + 96];
            float4 b0 = sb[lane];      float4 b1 = sb[lane + 32];
            float4 b2 = sb[lane + 64]; float4 b3 = sb[lane + 96];
            da[lane] = a0; da[lane + 32] = a1; da[lane + 64] = a2; da[lane + 96] = a3;
            db[lane] = b0; db[lane + 32] = b1; db[lane + 64] = b2; db[lane + 96] = b3;
        }
        return;
    }

    const int n = c - C_STUFF;

    const float bx1 = __ldg(&bbox[n * 4 + 0]);
    const float by1 = __ldg(&bbox[n * 4 + 1]);
    const float bx2 = __ldg(&bbox[n * 4 + 2]);
    const float by2 = __ldg(&bbox[n * 4 + 3]);
    const int   cls = __ldg(&cls_idx[n]);

    // paste box (floor) / crop box (trunc + round-half-even) — once per warp
    const int x1b = (int)floorf(bx1);
    const int y1b = (int)floorf(by1);
    const int x2b = (int)floorf(bx2);
    const int y2b = (int)floorf(by2);
    const int cy1 = (int)by1;
    const int cy2 = (int)rintf(by2) + 1;
    const int cx1 = (int)bx1;
    const int cx2 = (int)rintf(bx2) + 1;

    const int pylo = max(y1b, 0), pyhi = min(y2b + 1, H_SZ);
    const float bwf = (float)(x2b - x1b + 1);
    const float bhf = (float)(y2b - y1b + 1);
    const int xlo = max(x1b, 0);
    const int xhi = min(x2b + 1, W_SZ);
    const float invbw = (float)M_SZ / bwf;
    const float invbh = (float)M_SZ / bhf;

    const float* __restrict__ mtile =
        mask_logits + ((size_t)n * C_THING + (size_t)cls) * (M_SZ * M_SZ);
    const float* __restrict__ schan =
        sem_seg + (size_t)(C_STUFF + cls) * H_SZ * W_SZ;

    #pragma unroll
    for (int r = 0; r < ROWS_PW; ++r) {
        const int y = y0 + r;
        float4* __restrict__ orow = orow0 + r * 128;

        const bool in_paste = (y >= pylo) && (y < pyhi);
        const bool in_crop  = (y >= cy1) && (y < cy2);

        if (!in_paste && !in_crop) {
            const float4 z = make_float4(0.f, 0.f, 0.f, 0.f);
            orow[lane] = z; orow[lane + 32] = z;
            orow[lane + 64] = z; orow[lane + 96] = z;
            continue;
        }

        float4 vals[4];
        #pragma unroll
        for (int j = 0; j < 4; ++j) vals[j] = make_float4(0.f, 0.f, 0.f, 0.f);

        if (in_paste) {
            float my = ((float)y - (float)y1b + 0.5f) * invbh - 0.5f;
            my = fmaxf(my, 0.f);
            const float myf = floorf(my);
            const float fy  = my - myf;
            const int iy0 = min((int)myf,     M_SZ - 1);
            const int iy1 = min((int)myf + 1, M_SZ - 1);
            const float* __restrict__ mrow0 = mtile + iy0 * M_SZ;
            const float* __restrict__ mrow1 = mtile + iy1 * M_SZ;

            #pragma unroll
            for (int j = 0; j < 4; ++j) {
                const int xbase = (lane + 32 * j) * 4;
                if (xbase + 3 < xlo || xbase >= xhi) continue;
                float* v = &vals[j].x;
                #pragma unroll
                for (int e = 0; e < 4; ++e) {
                    const int x = xbase + e;
                    if (x >= xlo && x < xhi) {
                        float mx = ((float)x - (float)x1b + 0.5f) * invbw - 0.5f;
                        mx = fmaxf(mx, 0.f);
                        const float mxf = floorf(mx);
                        const float fx  = mx - mxf;
                        const int ix0 = min((int)mxf,     M_SZ - 1);
                        const int ix1 = min((int)mxf + 1, M_SZ - 1);
                        const float top = mrow0[ix0] * (1.f - fx) + mrow0[ix1] * fx;
                        const float bot = mrow1[ix0] * (1.f - fx) + mrow1[ix1] * fx;
                        v[e] = (1.f - fy) * top + fy * bot;
                    }
                }
            }
        }

        if (in_crop) {
            const float* __restrict__ srow = schan + (size_t)y * W_SZ;
            #pragma unroll
            for (int j = 0; j < 4; ++j) {
                const int xbase = (lane + 32 * j) * 4;
                if (xbase + 3 < cx1 || xbase >= cx2) continue;
                float* v = &vals[j].x;
                if (xbase >= cx1 && xbase + 3 < cx2) {
                    const float4 s = *(const float4*)(srow + xbase);
                    v[0] += s.x; v[1] += s.y; v[2] += s.z; v[3] += s.w;
                } else {
                    #pragma unroll
                    for (int e = 0; e < 4; ++e) {
                        const int x = xbase + e;
                        if (x >= cx1 && x < cx2) v[e] += __ldg(&srow[x]);
                    }
                }
            }
        }

        orow[lane]      = vals[0];
        orow[lane + 32] = vals[1];
        orow[lane + 64] = vals[2];
        orow[lane + 96] = vals[3];
    }
}

extern "C" void kernel_launch(void* const* d_in, const int* in_sizes, int n_in,
                              void* d_out, int out_size)
{
    const float* mask_logits = (const float*)d_in[0];
    const float* sem_seg     = (const float*)d_in[1];
    const float* bbox        = (const float*)d_in[2];
    const int*   cls_idx     = (const int*)d_in[3];
    float*       out         = (float*)d_out;

    const int total_rows = C_OUT * H_SZ;                       // 29952
    dim3 block(WARPS_PB * 32);                                 // 256
    dim3 grid(total_rows / (WARPS_PB * ROWS_PW));              // 936
    panoptic_all_kernel<<<grid, block>>>(mask_logits, sem_seg, bbox, cls_idx, out);
}

// round 7
// speedup vs baseline: 1.6243x; 1.6243x over previous
#include <cuda_runtime.h>
#include <cuda_bf16.h>

#define M_SZ    100
#define H_SZ    256
#define W_SZ    512
#define N_INST  64
#define C_THING 80
#define C_STUFF 53
#define C_OUT   (C_STUFF + N_INST)   // 117
#define WARPS_PB 8

// One warp per output row (512 floats = 128 float4). Lane l handles float4
// columns l, l+32, l+64, l+96 -> 4 independent ld/st per thread (MLP=4).
// Output stores use .cs (evict-first) so the 61MB output stream doesn't
// thrash the L2-resident sem_seg read set; streaming reads use __ldcs.
__global__ __launch_bounds__(WARPS_PB * 32)
void panoptic_all_kernel(const float* __restrict__ mask_logits,   // [N, C_THING, M, M]
                         const float* __restrict__ sem_seg,       // [1, C_STUFF+C_THING, H, W]
                         const float* __restrict__ bbox,          // [N, 4]
                         const int*   __restrict__ cls_idx,       // [N]
                         float* __restrict__ out)                 // [1, C_OUT, H, W]
{
    const int warp = threadIdx.x >> 5;
    const int lane = threadIdx.x & 31;
    const int grow = blockIdx.x * WARPS_PB + warp;          // row in [0, C_OUT*H)
    const int c    = grow >> 8;                              // H == 256
    const int y    = grow & (H_SZ - 1);

    float4* __restrict__ orow = (float4*)(out + (size_t)grow * W_SZ);

    if (c < C_STUFF) {
        // stuff channel: verbatim copy; streaming loads, evict-first stores
        const float4* __restrict__ srow =
            (const float4*)(sem_seg + (size_t)grow * W_SZ);
        float4 v0 = __ldcs(srow + lane);
        float4 v1 = __ldcs(srow + lane + 32);
        float4 v2 = __ldcs(srow + lane + 64);
        float4 v3 = __ldcs(srow + lane + 96);
        __stcs(orow + lane,      v0);
        __stcs(orow + lane + 32, v1);
        __stcs(orow + lane + 64, v2);
        __stcs(orow + lane + 96, v3);
        return;
    }

    const int n = c - C_STUFF;

    const float bx1 = __ldg(&bbox[n * 4 + 0]);
    const float by1 = __ldg(&bbox[n * 4 + 1]);
    const float bx2 = __ldg(&bbox[n * 4 + 2]);
    const float by2 = __ldg(&bbox[n * 4 + 3]);

    // paste box (floor) / crop box (trunc + round-half-even)
    const int y1b = (int)floorf(by1);
    const int y2b = (int)floorf(by2);
    const int cy1 = (int)by1;
    const int cy2 = (int)rintf(by2) + 1;

    const bool row_in_paste = (y >= max(y1b, 0)) && (y < min(y2b + 1, H_SZ));
    const bool row_in_crop  = (y >= cy1) && (y < cy2);

    if (!row_in_paste && !row_in_crop) {
        // pure zero row: 4 independent evict-first stores
        const float4 z = make_float4(0.f, 0.f, 0.f, 0.f);
        __stcs(orow + lane,      z);
        __stcs(orow + lane + 32, z);
        __stcs(orow + lane + 64, z);
        __stcs(orow + lane + 96, z);
        return;
    }

    const int cls = __ldg(&cls_idx[n]);
    const int x1b = (int)floorf(bx1);
    const int x2b = (int)floorf(bx2);

    float4 vals[4];
    #pragma unroll
    for (int j = 0; j < 4; ++j) vals[j] = make_float4(0.f, 0.f, 0.f, 0.f);

    if (row_in_paste) {
        const float bwf = (float)(x2b - x1b + 1);
        const float bhf = (float)(y2b - y1b + 1);
        const float* __restrict__ mtile =
            mask_logits + ((size_t)n * C_THING + (size_t)cls) * (M_SZ * M_SZ);

        float my = ((float)y - (float)y1b + 0.5f) * ((float)M_SZ / bhf) - 0.5f;
        my = fmaxf(my, 0.f);
        const float myf = floorf(my);
        const float fy  = my - myf;
        const int iy0 = min((int)myf,     M_SZ - 1);
        const int iy1 = min((int)myf + 1, M_SZ - 1);
        const float* __restrict__ mrow0 = mtile + iy0 * M_SZ;
        const float* __restrict__ mrow1 = mtile + iy1 * M_SZ;

        const int xlo = max(x1b, 0);
        const int xhi = min(x2b + 1, W_SZ);
        const float invbw = (float)M_SZ / bwf;

        #pragma unroll
        for (int j = 0; j < 4; ++j) {
            const int xbase = (lane + 32 * j) * 4;
            if (xbase + 3 < xlo || xbase >= xhi) continue;   // fully outside
            float* v = &vals[j].x;
            #pragma unroll
            for (int e = 0; e < 4; ++e) {
                const int x = xbase + e;
                if (x >= xlo && x < xhi) {
                    float mx = ((float)x - (float)x1b + 0.5f) * invbw - 0.5f;
                    mx = fmaxf(mx, 0.f);
                    const float mxf = floorf(mx);
                    const float fx  = mx - mxf;
                    const int ix0 = min((int)mxf,     M_SZ - 1);
                    const int ix1 = min((int)mxf + 1, M_SZ - 1);
                    const float top = mrow0[ix0] * (1.f - fx) + mrow0[ix1] * fx;
                    const float bot = mrow1[ix0] * (1.f - fx) + mrow1[ix1] * fx;
                    v[e] = (1.f - fy) * top + fy * bot;
                }
            }
        }
    }

    if (row_in_crop) {
        const int cx1 = (int)bx1;
        const int cx2 = (int)rintf(bx2) + 1;
        const float* __restrict__ srow =
            sem_seg + ((size_t)(C_STUFF + cls) * H_SZ + (size_t)y) * W_SZ;
        #pragma unroll
        for (int j = 0; j < 4; ++j) {
            const int xbase = (lane + 32 * j) * 4;
            if (xbase + 3 < cx1 || xbase >= cx2) continue;   // fully outside
            float* v = &vals[j].x;
            if (xbase >= cx1 && xbase + 3 < cx2) {
                const float4 s = __ldcs((const float4*)(srow + xbase));
                v[0] += s.x; v[1] += s.y; v[2] += s.z; v[3] += s.w;
            } else {
                #pragma unroll
                for (int e = 0; e < 4; ++e) {
                    const int x = xbase + e;
                    if (x >= cx1 && x < cx2) v[e] += __ldcs(&srow[x]);
                }
            }
        }
    }

    __stcs(orow + lane,      vals[0]);
    __stcs(orow + lane + 32, vals[1]);
    __stcs(orow + lane + 64, vals[2]);
    __stcs(orow + lane + 96, vals[3]);
}

extern "C" void kernel_launch(void* const* d_in, const int* in_sizes, int n_in,
                              void* d_out, int out_size)
{
    const float* mask_logits = (const float*)d_in[0];
    const float* sem_seg     = (const float*)d_in[1];
    const float* bbox        = (const float*)d_in[2];
    const int*   cls_idx     = (const int*)d_in[3];
    float*       out         = (float*)d_out;

    const int total_rows = C_OUT * H_SZ;                 // 29952
    dim3 block(WARPS_PB * 32);                           // 256
    dim3 grid(total_rows / WARPS_PB);                    // 3744
    panoptic_all_kernel<<<grid, block>>>(mask_logits, sem_seg, bbox, cls_idx, out);
}